// round 15
// baseline (speedup 1.0000x reference)
#include <cuda_runtime.h>
#include <math.h>

// FilteredNoise: B=64 banks, F=4097 frames, FCL=65 coeffs, FL=64 frame len.
// IR length 129 (linear-phase), per-frame conv length 192, overlap-add hop 64,
// output truncated to 262144 samples per bank (frame 4096 fully truncated).
//
// Key algebra:
//   zp = irfft(fr, 129) is symmetric: zp[u] = zp[129-u]
//   roll by 64  =>  lp[t] = zp[|t-64|]   (65 unique values per frame)
//   wir[t] = lp[t] * hann_periodic_129[t]
//   filtered[j] = sum_i n[i]*wir[j-i],  n = 2*noise-1
//   out sample s gets contributions only from frames {s/64 - 2, -1, 0}.
//
// Conv layout: padded IR Wfull[0..255] (wir at [64,193), zeros elsewhere) is
// stored PARITY-DEINTERLEAVED per frame: E[e]=Wfull[2e], O[o]=Wfull[2o+1].
// Each lane owns 6 outputs (j0=6*lane); every tap fetch then has uniform
// parity across the warp and lands at shared-word stride 3 (odd) in one copy:
// bank-conflict-free. Overlap-add accumulator deinterleaved the same way.
//
// R13->R14: cosine matrix M is read straight from global via __ldg (identical
// across CTAs, L1-resident) instead of a 17.7KB per-CTA smem copy; smem drops
// to ~27.7KB and __launch_bounds__(256,5) caps regs at 48 -> 40 warps/SM.

#define NBATCH   64
#define NFRAMES  4097
#define FCL      65
#define FL       64
#define IRLEN    129
#define SAMPLES  262144
#define NB       32          // output 64-blocks per CTA
#define CHUNKS   128         // NB*CHUNKS = 4096 blocks = SAMPLES/FL
#define NTHREADS 256
#define MAXNF    12          // max frames per residue round
#define MSTRIDE  68          // cosine-matrix row stride (float4-aligned rows)
#define FSTRIDE  68          // sFr row stride (16B aligned)
#define OOFF     145         // odd-copy word offset within a wir row (== 16+1 mod 32)
#define WSTRIDE2 273         // deinterleaved wir row: E[0..128) | pad | O at [145,273)
#define HACC     1024        // half-size of the deinterleaved accumulator
#define LN10F    2.302585092994046f

__device__ __align__(16) float g_M[FCL * MSTRIDE]; // g_M[d*68+k] = c_k/129 * cos(2*pi*k*d/129)
__device__ float g_win[132];                       // periodic hann, length 129 (+pad)

__global__ void init_tables() {
    int tid = threadIdx.x;
    for (int idx = tid; idx < FCL * MSTRIDE; idx += blockDim.x) {
        int d = idx / MSTRIDE, k = idx - d * MSTRIDE;
        float v = 0.0f;
        if (k < FCL) {
            double c = (k == 0) ? 1.0 : 2.0;
            v = (float)((c / 129.0) * cos(2.0 * M_PI * (double)k * (double)d / 129.0));
        }
        g_M[idx] = v;
    }
    for (int t = tid; t < 132; t += blockDim.x) {
        float v = 0.0f;
        if (t < IRLEN) v = (float)(0.5 * (1.0 - cos(2.0 * M_PI * (double)t / 129.0)));
        g_win[t] = v;
    }
}

__global__ __launch_bounds__(NTHREADS, 5)
void filtered_noise_kernel(const float* __restrict__ coef,
                           const float* __restrict__ noise,
                           float* __restrict__ out)
{
    __shared__ float sWin[132];                           //   528 B
    __shared__ __align__(16) float sWir[MAXNF][WSTRIDE2]; // 13104 B (E|pad|O per frame)
    __shared__ __align__(16) float sN[MAXNF][FL];         //  3072 B
    __shared__ __align__(16) float sFr[MAXNF][FSTRIDE];   //  3264 B
    __shared__ __align__(16) float sAccE[HACC];           //  4096 B (even output samples)
    __shared__ __align__(16) float sAccO[HACC];           //  4096 B (odd samples) ~27.6KB

    const int tid = threadIdx.x;
    const int b   = blockIdx.y;
    const int f0  = blockIdx.x * NB;          // first output block of this chunk

    for (int i = tid; i < 132; i += NTHREADS) sWin[i] = g_win[i];
    for (int i = tid; i < MAXNF * WSTRIDE2; i += NTHREADS) (&sWir[0][0])[i] = 0.0f;
    for (int i = tid; i < HACC; i += NTHREADS) { sAccE[i] = 0.0f; sAccO[i] = 0.0f; }
    __syncthreads();

    const int g_start = (f0 - 2 > 0) ? (f0 - 2) : 0;
    const int g_end   = f0 + NB;              // frames [g_start, g_end) feed this chunk
    const int wid  = tid >> 5;
    const int lane = tid & 31;

    // Three rounds by frame residue mod 3: frames within a round have disjoint
    // 192-sample output windows, so accumulation is race-free.
    for (int r = 0; r < 3; ++r) {
        int g0 = g_start + (((r - g_start) % 3) + 3) % 3;
        int nf = (g0 < g_end) ? ((g_end - 1 - g0) / 3 + 1) : 0;

        // -------- phase 1a: modified sigmoid + noise load --------
        for (int idx = tid; idx < nf * FCL; idx += NTHREADS) {
            int fi = idx / FCL, k = idx - fi * FCL;
            int g = g0 + 3 * fi;
            float x = coef[((size_t)b * NFRAMES + g) * FCL + k];
            float s = 1.0f / (1.0f + __expf(-x));
            sFr[fi][k] = 2.0f * __expf(LN10F * __logf(s)) + 1e-7f;
        }
        for (int idx = tid; idx < nf * FL; idx += NTHREADS) {
            int fi = idx >> 6, i = idx & 63;
            int g = g0 + 3 * fi;
            sN[fi][i] = 2.0f * noise[((size_t)b * NFRAMES + g) * FL + i] - 1.0f;
        }
        __syncthreads();

        // -------- phase 1b: 65-pt cosine matvec, float4 + frame-pair tiling --------
        // M rows come straight from global (__ldg, L1-resident, shared by all
        // CTAs). fr rows are broadcast float4 LDS. Writes go into the
        // deinterleaved layout: even-d -> E half, odd-d -> O half (disjoint
        // bank halves: conflict-free mixed-parity stores).
        {
            int npair = (nf + 1) >> 1;
            for (int idx = tid; idx < npair * FCL; idx += NTHREADS) {
                int p = idx / FCL, d = idx - p * FCL;
                int fi0 = 2 * p;
                const float4* M4 = (const float4*)&g_M[d * MSTRIDE];
                const float4* F0 = (const float4*)&sFr[fi0][0];
                const float4* F1 = (const float4*)&sFr[fi0 + 1][0];
                float a0e = 0.f, a0o = 0.f, a1e = 0.f, a1o = 0.f;
                #pragma unroll
                for (int k4 = 0; k4 < 16; ++k4) {
                    float4 m = __ldg(&M4[k4]);
                    float4 x = F0[k4];
                    float4 y = F1[k4];
                    a0e = fmaf(m.x, x.x, a0e); a0o = fmaf(m.y, x.y, a0o);
                    a0e = fmaf(m.z, x.z, a0e); a0o = fmaf(m.w, x.w, a0o);
                    a1e = fmaf(m.x, y.x, a1e); a1o = fmaf(m.y, y.y, a1o);
                    a1e = fmaf(m.z, y.z, a1e); a1o = fmaf(m.w, y.w, a1o);
                }
                float m64 = __ldg(&g_M[d * MSTRIDE + 64]);
                float a0 = a0e + a0o + m64 * sFr[fi0][64];
                float a1 = a1e + a1o + m64 * sFr[fi0 + 1][64];
                float whi = sWin[64 + d], wlo = sWin[64 - d];
                // Wfull[128+d] and Wfull[128-d] both have parity(d).
                int hiAddr, loAddr;
                if (d & 1) { hiAddr = OOFF + ((127 + d) >> 1); loAddr = OOFF + ((127 - d) >> 1); }
                else       { hiAddr = 64 + (d >> 1);           loAddr = 64 - (d >> 1); }
                sWir[fi0][hiAddr]     = a0 * whi;
                sWir[fi0][loAddr]     = a0 * wlo;
                sWir[fi0 + 1][hiAddr] = a1 * whi;
                sWir[fi0 + 1][loAddr] = a1 * wlo;
            }
        }
        __syncthreads();

        // -------- phase 2: direct conv + overlap-add, 6 outputs/lane --------
        // lane owns j0=6*lane..+5; rolling 6-reg window, one fresh tap per step.
        // Fresh tap index 64+j0-(i+1) has uniform parity across the warp:
        //   i even -> O[31+3l-i/2],  i odd -> E[31+3l-(i-1)/2]   (stride 3, no conflicts)
        for (int pass = 0; pass * 8 < nf; ++pass) {
            int fi = pass * 8 + wid;
            if (fi < nf) {
                int g  = g0 + 3 * fi;
                int t3 = 3 * lane;
                const float*  E  = &sWir[fi][0];
                const float*  O  = &sWir[fi][OOFF];
                const float4* N4 = (const float4*)&sN[fi][0];
                // init window: w_r = Wfull[64+6*lane+r]
                float w0 = E[32 + t3], w1 = O[32 + t3], w2 = E[33 + t3];
                float w3 = O[33 + t3], w4 = E[34 + t3], w5 = O[34 + t3];
                float a0 = 0.f, a1 = 0.f, a2 = 0.f, a3 = 0.f, a4 = 0.f, a5 = 0.f;
                #pragma unroll
                for (int i4 = 0; i4 < 16; ++i4) {
                    float4 nv = N4[i4];
                    int k2 = 2 * i4;             // i = 4*i4 -> k = i/2 = 2*i4
                    float f0t = O[31 + t3 - k2];        // fresh for i=4*i4   (even)
                    float f1t = E[31 + t3 - k2];        // fresh for i=4*i4+1 (odd)
                    float f2t = O[30 + t3 - k2];        // fresh for i=4*i4+2
                    float f3t = E[30 + t3 - k2];        // fresh for i=4*i4+3
                    a0 = fmaf(nv.x, w0, a0); a1 = fmaf(nv.x, w1, a1); a2 = fmaf(nv.x, w2, a2);
                    a3 = fmaf(nv.x, w3, a3); a4 = fmaf(nv.x, w4, a4); a5 = fmaf(nv.x, w5, a5);
                    w5 = w4; w4 = w3; w3 = w2; w2 = w1; w1 = w0; w0 = f0t;
                    a0 = fmaf(nv.y, w0, a0); a1 = fmaf(nv.y, w1, a1); a2 = fmaf(nv.y, w2, a2);
                    a3 = fmaf(nv.y, w3, a3); a4 = fmaf(nv.y, w4, a4); a5 = fmaf(nv.y, w5, a5);
                    w5 = w4; w4 = w3; w3 = w2; w2 = w1; w1 = w0; w0 = f1t;
                    a0 = fmaf(nv.z, w0, a0); a1 = fmaf(nv.z, w1, a1); a2 = fmaf(nv.z, w2, a2);
                    a3 = fmaf(nv.z, w3, a3); a4 = fmaf(nv.z, w4, a4); a5 = fmaf(nv.z, w5, a5);
                    w5 = w4; w4 = w3; w3 = w2; w2 = w1; w1 = w0; w0 = f2t;
                    a0 = fmaf(nv.w, w0, a0); a1 = fmaf(nv.w, w1, a1); a2 = fmaf(nv.w, w2, a2);
                    a3 = fmaf(nv.w, w3, a3); a4 = fmaf(nv.w, w4, a4); a5 = fmaf(nv.w, w5, a5);
                    w5 = w4; w4 = w3; w3 = w2; w2 = w1; w1 = w0; w0 = f3t;
                }
                // overlap-add: output element base+r, base = (g-f0)*64 + 6*lane (even).
                // r even -> sAccE[b2 + r/2], r odd -> sAccO[b2 + r/2]  (stride 3)
                int b2 = (g - f0) * 32 + t3;     // halved index, in [-64, 1085]
                if (b2 >= 0 && b2 + 2 < HACC) {
                    sAccE[b2]     += a0; sAccO[b2]     += a1;
                    sAccE[b2 + 1] += a2; sAccO[b2 + 1] += a3;
                    sAccE[b2 + 2] += a4; sAccO[b2 + 2] += a5;
                } else {
                    if (b2     >= 0 && b2     < HACC) { sAccE[b2]     += a0; sAccO[b2]     += a1; }
                    if (b2 + 1 >= 0 && b2 + 1 < HACC) { sAccE[b2 + 1] += a2; sAccO[b2 + 1] += a3; }
                    if (b2 + 2 >= 0 && b2 + 2 < HACC) { sAccE[b2 + 2] += a4; sAccO[b2 + 2] += a5; }
                }
            }
        }
        __syncthreads();
    }

    // epilogue: re-interleave accumulator halves and store as float2
    float2* op2 = (float2*)(out + (size_t)b * SAMPLES + (size_t)f0 * FL);
    for (int i = tid; i < HACC; i += NTHREADS) {
        float2 v; v.x = sAccE[i]; v.y = sAccO[i];
        op2[i] = v;
    }
}

extern "C" void kernel_launch(void* const* d_in, const int* in_sizes, int n_in,
                              void* d_out, int out_size) {
    const float* coef  = (const float*)d_in[0];
    const float* noise = (const float*)d_in[1];
    if (in_sizes[0] != NBATCH * NFRAMES * FCL) {
        const float* t = coef; coef = noise; noise = t;
    }
    init_tables<<<1, 256>>>();
    dim3 grid(CHUNKS, NBATCH);
    filtered_noise_kernel<<<grid, NTHREADS>>>(coef, noise, (float*)d_out);
}

// round 16
// speedup vs baseline: 1.0459x; 1.0459x over previous
#include <cuda_runtime.h>
#include <math.h>

// FilteredNoise: B=64 banks, F=4097 frames, FCL=65 coeffs, FL=64 frame len.
// IR length 129 (linear-phase), per-frame conv length 192, overlap-add hop 64,
// output truncated to 262144 samples per bank (frame 4096 fully truncated).
//
// Key algebra:
//   zp = irfft(fr, 129) is symmetric: zp[u] = zp[129-u]
//   roll by 64  =>  lp[t] = zp[|t-64|]   (65 unique values per frame)
//   wir[t] = lp[t] * hann_periodic_129[t]
//   filtered[j] = sum_i n[i]*wir[j-i],  n = 2*noise-1
//   out sample s gets contributions only from frames {s/64 - 2, -1, 0}.
//
// Conv layout: padded IR Wfull[0..255] (wir at [64,193), zeros elsewhere) is
// stored PARITY-DEINTERLEAVED per frame: E[e]=Wfull[2e], O[o]=Wfull[2o+1].
// Each lane owns 6 outputs (j0=6*lane); every tap fetch then has uniform
// parity across the warp and lands at shared-word stride 3 (odd) in one copy:
// bank-conflict-free. Overlap-add accumulator deinterleaved the same way.
//
// R13->R14: cosine matrix M is read straight from global via __ldg (identical
// across CTAs, L1-resident) instead of a 17.7KB per-CTA smem copy; smem drops
// to ~27.7KB and __launch_bounds__(256,5) caps regs at 48 -> 40 warps/SM.

#define NBATCH   64
#define NFRAMES  4097
#define FCL      65
#define FL       64
#define IRLEN    129
#define SAMPLES  262144
#define NB       32          // output 64-blocks per CTA
#define CHUNKS   128         // NB*CHUNKS = 4096 blocks = SAMPLES/FL
#define NTHREADS 256
#define MAXNF    12          // max frames per residue round
#define MSTRIDE  68          // cosine-matrix row stride (float4-aligned rows)
#define FSTRIDE  68          // sFr row stride (16B aligned)
#define OOFF     145         // odd-copy word offset within a wir row (== 16+1 mod 32)
#define WSTRIDE2 273         // deinterleaved wir row: E[0..128) | pad | O at [145,273)
#define HACC     1024        // half-size of the deinterleaved accumulator
#define LN10F    2.302585092994046f

__device__ __align__(16) float g_M[FCL * MSTRIDE]; // g_M[d*68+k] = c_k/129 * cos(2*pi*k*d/129)
__device__ float g_win[132];                       // periodic hann, length 129 (+pad)

__global__ void init_tables() {
    int tid = threadIdx.x;
    for (int idx = tid; idx < FCL * MSTRIDE; idx += blockDim.x) {
        int d = idx / MSTRIDE, k = idx - d * MSTRIDE;
        float v = 0.0f;
        if (k < FCL) {
            double c = (k == 0) ? 1.0 : 2.0;
            v = (float)((c / 129.0) * cos(2.0 * M_PI * (double)k * (double)d / 129.0));
        }
        g_M[idx] = v;
    }
    for (int t = tid; t < 132; t += blockDim.x) {
        float v = 0.0f;
        if (t < IRLEN) v = (float)(0.5 * (1.0 - cos(2.0 * M_PI * (double)t / 129.0)));
        g_win[t] = v;
    }
}

__global__ __launch_bounds__(NTHREADS, 5)
void filtered_noise_kernel(const float* __restrict__ coef,
                           const float* __restrict__ noise,
                           float* __restrict__ out)
{
    __shared__ float sWin[132];                           //   528 B
    __shared__ __align__(16) float sWir[MAXNF][WSTRIDE2]; // 13104 B (E|pad|O per frame)
    __shared__ __align__(16) float sN[MAXNF][FL];         //  3072 B
    __shared__ __align__(16) float sFr[MAXNF][FSTRIDE];   //  3264 B
    __shared__ __align__(16) float sAccE[HACC];           //  4096 B (even output samples)
    __shared__ __align__(16) float sAccO[HACC];           //  4096 B (odd samples) ~27.6KB

    const int tid = threadIdx.x;
    const int b   = blockIdx.y;
    const int f0  = blockIdx.x * NB;          // first output block of this chunk

    for (int i = tid; i < 132; i += NTHREADS) sWin[i] = g_win[i];
    for (int i = tid; i < MAXNF * WSTRIDE2; i += NTHREADS) (&sWir[0][0])[i] = 0.0f;
    for (int i = tid; i < HACC; i += NTHREADS) { sAccE[i] = 0.0f; sAccO[i] = 0.0f; }
    __syncthreads();

    const int g_start = (f0 - 2 > 0) ? (f0 - 2) : 0;
    const int g_end   = f0 + NB;              // frames [g_start, g_end) feed this chunk
    const int wid  = tid >> 5;
    const int lane = tid & 31;

    // Three rounds by frame residue mod 3: frames within a round have disjoint
    // 192-sample output windows, so accumulation is race-free.
    for (int r = 0; r < 3; ++r) {
        int g0 = g_start + (((r - g_start) % 3) + 3) % 3;
        int nf = (g0 < g_end) ? ((g_end - 1 - g0) / 3 + 1) : 0;

        // -------- phase 1a: modified sigmoid + noise load --------
        for (int idx = tid; idx < nf * FCL; idx += NTHREADS) {
            int fi = idx / FCL, k = idx - fi * FCL;
            int g = g0 + 3 * fi;
            float x = coef[((size_t)b * NFRAMES + g) * FCL + k];
            float s = 1.0f / (1.0f + __expf(-x));
            sFr[fi][k] = 2.0f * __expf(LN10F * __logf(s)) + 1e-7f;
        }
        for (int idx = tid; idx < nf * FL; idx += NTHREADS) {
            int fi = idx >> 6, i = idx & 63;
            int g = g0 + 3 * fi;
            sN[fi][i] = 2.0f * noise[((size_t)b * NFRAMES + g) * FL + i] - 1.0f;
        }
        __syncthreads();

        // -------- phase 1b: 65-pt cosine matvec, float4 + frame-pair tiling --------
        // M rows come straight from global (__ldg, L1-resident, shared by all
        // CTAs). fr rows are broadcast float4 LDS. Writes go into the
        // deinterleaved layout: even-d -> E half, odd-d -> O half (disjoint
        // bank halves: conflict-free mixed-parity stores).
        {
            int npair = (nf + 1) >> 1;
            for (int idx = tid; idx < npair * FCL; idx += NTHREADS) {
                int p = idx / FCL, d = idx - p * FCL;
                int fi0 = 2 * p;
                const float4* M4 = (const float4*)&g_M[d * MSTRIDE];
                const float4* F0 = (const float4*)&sFr[fi0][0];
                const float4* F1 = (const float4*)&sFr[fi0 + 1][0];
                float a0e = 0.f, a0o = 0.f, a1e = 0.f, a1o = 0.f;
                #pragma unroll
                for (int k4 = 0; k4 < 16; ++k4) {
                    float4 m = __ldg(&M4[k4]);
                    float4 x = F0[k4];
                    float4 y = F1[k4];
                    a0e = fmaf(m.x, x.x, a0e); a0o = fmaf(m.y, x.y, a0o);
                    a0e = fmaf(m.z, x.z, a0e); a0o = fmaf(m.w, x.w, a0o);
                    a1e = fmaf(m.x, y.x, a1e); a1o = fmaf(m.y, y.y, a1o);
                    a1e = fmaf(m.z, y.z, a1e); a1o = fmaf(m.w, y.w, a1o);
                }
                float m64 = __ldg(&g_M[d * MSTRIDE + 64]);
                float a0 = a0e + a0o + m64 * sFr[fi0][64];
                float a1 = a1e + a1o + m64 * sFr[fi0 + 1][64];
                float whi = sWin[64 + d], wlo = sWin[64 - d];
                // Wfull[128+d] and Wfull[128-d] both have parity(d).
                int hiAddr, loAddr;
                if (d & 1) { hiAddr = OOFF + ((127 + d) >> 1); loAddr = OOFF + ((127 - d) >> 1); }
                else       { hiAddr = 64 + (d >> 1);           loAddr = 64 - (d >> 1); }
                sWir[fi0][hiAddr]     = a0 * whi;
                sWir[fi0][loAddr]     = a0 * wlo;
                sWir[fi0 + 1][hiAddr] = a1 * whi;
                sWir[fi0 + 1][loAddr] = a1 * wlo;
            }
        }
        __syncthreads();

        // -------- phase 2: direct conv + overlap-add, 6 outputs/lane --------
        // lane owns j0=6*lane..+5; rolling 6-reg window, one fresh tap per step.
        // Fresh tap index 64+j0-(i+1) has uniform parity across the warp:
        //   i even -> O[31+3l-i/2],  i odd -> E[31+3l-(i-1)/2]   (stride 3, no conflicts)
        for (int pass = 0; pass * 8 < nf; ++pass) {
            int fi = pass * 8 + wid;
            if (fi < nf) {
                int g  = g0 + 3 * fi;
                int t3 = 3 * lane;
                const float*  E  = &sWir[fi][0];
                const float*  O  = &sWir[fi][OOFF];
                const float4* N4 = (const float4*)&sN[fi][0];
                // init window: w_r = Wfull[64+6*lane+r]
                float w0 = E[32 + t3], w1 = O[32 + t3], w2 = E[33 + t3];
                float w3 = O[33 + t3], w4 = E[34 + t3], w5 = O[34 + t3];
                float a0 = 0.f, a1 = 0.f, a2 = 0.f, a3 = 0.f, a4 = 0.f, a5 = 0.f;
                #pragma unroll
                for (int i4 = 0; i4 < 16; ++i4) {
                    float4 nv = N4[i4];
                    int k2 = 2 * i4;             // i = 4*i4 -> k = i/2 = 2*i4
                    float f0t = O[31 + t3 - k2];        // fresh for i=4*i4   (even)
                    float f1t = E[31 + t3 - k2];        // fresh for i=4*i4+1 (odd)
                    float f2t = O[30 + t3 - k2];        // fresh for i=4*i4+2
                    float f3t = E[30 + t3 - k2];        // fresh for i=4*i4+3
                    a0 = fmaf(nv.x, w0, a0); a1 = fmaf(nv.x, w1, a1); a2 = fmaf(nv.x, w2, a2);
                    a3 = fmaf(nv.x, w3, a3); a4 = fmaf(nv.x, w4, a4); a5 = fmaf(nv.x, w5, a5);
                    w5 = w4; w4 = w3; w3 = w2; w2 = w1; w1 = w0; w0 = f0t;
                    a0 = fmaf(nv.y, w0, a0); a1 = fmaf(nv.y, w1, a1); a2 = fmaf(nv.y, w2, a2);
                    a3 = fmaf(nv.y, w3, a3); a4 = fmaf(nv.y, w4, a4); a5 = fmaf(nv.y, w5, a5);
                    w5 = w4; w4 = w3; w3 = w2; w2 = w1; w1 = w0; w0 = f1t;
                    a0 = fmaf(nv.z, w0, a0); a1 = fmaf(nv.z, w1, a1); a2 = fmaf(nv.z, w2, a2);
                    a3 = fmaf(nv.z, w3, a3); a4 = fmaf(nv.z, w4, a4); a5 = fmaf(nv.z, w5, a5);
                    w5 = w4; w4 = w3; w3 = w2; w2 = w1; w1 = w0; w0 = f2t;
                    a0 = fmaf(nv.w, w0, a0); a1 = fmaf(nv.w, w1, a1); a2 = fmaf(nv.w, w2, a2);
                    a3 = fmaf(nv.w, w3, a3); a4 = fmaf(nv.w, w4, a4); a5 = fmaf(nv.w, w5, a5);
                    w5 = w4; w4 = w3; w3 = w2; w2 = w1; w1 = w0; w0 = f3t;
                }
                // overlap-add: output element base+r, base = (g-f0)*64 + 6*lane (even).
                // r even -> sAccE[b2 + r/2], r odd -> sAccO[b2 + r/2]  (stride 3)
                int b2 = (g - f0) * 32 + t3;     // halved index, in [-64, 1085]
                if (b2 >= 0 && b2 + 2 < HACC) {
                    sAccE[b2]     += a0; sAccO[b2]     += a1;
                    sAccE[b2 + 1] += a2; sAccO[b2 + 1] += a3;
                    sAccE[b2 + 2] += a4; sAccO[b2 + 2] += a5;
                } else {
                    if (b2     >= 0 && b2     < HACC) { sAccE[b2]     += a0; sAccO[b2]     += a1; }
                    if (b2 + 1 >= 0 && b2 + 1 < HACC) { sAccE[b2 + 1] += a2; sAccO[b2 + 1] += a3; }
                    if (b2 + 2 >= 0 && b2 + 2 < HACC) { sAccE[b2 + 2] += a4; sAccO[b2 + 2] += a5; }
                }
            }
        }
        __syncthreads();
    }

    // epilogue: re-interleave accumulator halves and store as float2
    float2* op2 = (float2*)(out + (size_t)b * SAMPLES + (size_t)f0 * FL);
    for (int i = tid; i < HACC; i += NTHREADS) {
        float2 v; v.x = sAccE[i]; v.y = sAccO[i];
        op2[i] = v;
    }
}

extern "C" void kernel_launch(void* const* d_in, const int* in_sizes, int n_in,
                              void* d_out, int out_size) {
    const float* coef  = (const float*)d_in[0];
    const float* noise = (const float*)d_in[1];
    if (in_sizes[0] != NBATCH * NFRAMES * FCL) {
        const float* t = coef; coef = noise; noise = t;
    }
    init_tables<<<1, 256>>>();
    dim3 grid(CHUNKS, NBATCH);
    filtered_noise_kernel<<<grid, NTHREADS>>>(coef, noise, (float*)d_out);
}

// round 17
// speedup vs baseline: 1.0514x; 1.0053x over previous
#include <cuda_runtime.h>
#include <math.h>

// FilteredNoise: B=64 banks, F=4097 frames, FCL=65 coeffs, FL=64 frame len.
// IR length 129 (linear-phase), per-frame conv length 192, overlap-add hop 64,
// output truncated to 262144 samples per bank (frame 4096 fully truncated).
//
// Key algebra:
//   zp = irfft(fr, 129) is symmetric: zp[u] = zp[129-u]
//   roll by 64  =>  lp[t] = zp[|t-64|]   (65 unique values per frame)
//   wir[t] = lp[t] * hann_periodic_129[t]
//   filtered[j] = sum_i n[i]*wir[j-i],  n = 2*noise-1
//   out sample s gets contributions only from frames {s/64 - 2, -1, 0}.
//
// Conv layout: padded IR Wfull[0..255] (wir at [64,193), zeros elsewhere) is
// stored PARITY-DEINTERLEAVED per frame: E[e]=Wfull[2e], O[o]=Wfull[2o+1].
// Each lane owns 6 outputs (j0=6*lane); every tap fetch then has uniform
// parity across the warp and lands at shared-word stride 3 (odd) in one copy:
// bank-conflict-free. Overlap-add accumulator deinterleaved the same way.
//
// R13->R14: cosine matrix M is read straight from global via __ldg (identical
// across CTAs, L1-resident) instead of a 17.7KB per-CTA smem copy; smem drops
// to ~27.7KB and __launch_bounds__(256,5) caps regs at 48 -> 40 warps/SM.

#define NBATCH   64
#define NFRAMES  4097
#define FCL      65
#define FL       64
#define IRLEN    129
#define SAMPLES  262144
#define NB       32          // output 64-blocks per CTA
#define CHUNKS   128         // NB*CHUNKS = 4096 blocks = SAMPLES/FL
#define NTHREADS 256
#define MAXNF    12          // max frames per residue round
#define MSTRIDE  68          // cosine-matrix row stride (float4-aligned rows)
#define FSTRIDE  68          // sFr row stride (16B aligned)
#define OOFF     145         // odd-copy word offset within a wir row (== 16+1 mod 32)
#define WSTRIDE2 273         // deinterleaved wir row: E[0..128) | pad | O at [145,273)
#define HACC     1024        // half-size of the deinterleaved accumulator
#define LN10F    2.302585092994046f

__device__ __align__(16) float g_M[FCL * MSTRIDE]; // g_M[d*68+k] = c_k/129 * cos(2*pi*k*d/129)
__device__ float g_win[132];                       // periodic hann, length 129 (+pad)

__global__ void init_tables() {
    int tid = threadIdx.x;
    for (int idx = tid; idx < FCL * MSTRIDE; idx += blockDim.x) {
        int d = idx / MSTRIDE, k = idx - d * MSTRIDE;
        float v = 0.0f;
        if (k < FCL) {
            double c = (k == 0) ? 1.0 : 2.0;
            v = (float)((c / 129.0) * cos(2.0 * M_PI * (double)k * (double)d / 129.0));
        }
        g_M[idx] = v;
    }
    for (int t = tid; t < 132; t += blockDim.x) {
        float v = 0.0f;
        if (t < IRLEN) v = (float)(0.5 * (1.0 - cos(2.0 * M_PI * (double)t / 129.0)));
        g_win[t] = v;
    }
}

__global__ __launch_bounds__(NTHREADS, 5)
void filtered_noise_kernel(const float* __restrict__ coef,
                           const float* __restrict__ noise,
                           float* __restrict__ out)
{
    __shared__ float sWin[132];                           //   528 B
    __shared__ __align__(16) float sWir[MAXNF][WSTRIDE2]; // 13104 B (E|pad|O per frame)
    __shared__ __align__(16) float sN[MAXNF][FL];         //  3072 B
    __shared__ __align__(16) float sFr[MAXNF][FSTRIDE];   //  3264 B
    __shared__ __align__(16) float sAccE[HACC];           //  4096 B (even output samples)
    __shared__ __align__(16) float sAccO[HACC];           //  4096 B (odd samples) ~27.6KB

    const int tid = threadIdx.x;
    const int b   = blockIdx.y;
    const int f0  = blockIdx.x * NB;          // first output block of this chunk

    for (int i = tid; i < 132; i += NTHREADS) sWin[i] = g_win[i];
    for (int i = tid; i < MAXNF * WSTRIDE2; i += NTHREADS) (&sWir[0][0])[i] = 0.0f;
    for (int i = tid; i < HACC; i += NTHREADS) { sAccE[i] = 0.0f; sAccO[i] = 0.0f; }
    __syncthreads();

    const int g_start = (f0 - 2 > 0) ? (f0 - 2) : 0;
    const int g_end   = f0 + NB;              // frames [g_start, g_end) feed this chunk
    const int wid  = tid >> 5;
    const int lane = tid & 31;

    // Three rounds by frame residue mod 3: frames within a round have disjoint
    // 192-sample output windows, so accumulation is race-free.
    for (int r = 0; r < 3; ++r) {
        int g0 = g_start + (((r - g_start) % 3) + 3) % 3;
        int nf = (g0 < g_end) ? ((g_end - 1 - g0) / 3 + 1) : 0;

        // -------- phase 1a: modified sigmoid + noise load --------
        for (int idx = tid; idx < nf * FCL; idx += NTHREADS) {
            int fi = idx / FCL, k = idx - fi * FCL;
            int g = g0 + 3 * fi;
            float x = coef[((size_t)b * NFRAMES + g) * FCL + k];
            float s = 1.0f / (1.0f + __expf(-x));
            sFr[fi][k] = 2.0f * __expf(LN10F * __logf(s)) + 1e-7f;
        }
        for (int idx = tid; idx < nf * FL; idx += NTHREADS) {
            int fi = idx >> 6, i = idx & 63;
            int g = g0 + 3 * fi;
            sN[fi][i] = 2.0f * noise[((size_t)b * NFRAMES + g) * FL + i] - 1.0f;
        }
        __syncthreads();

        // -------- phase 1b: 65-pt cosine matvec, float4 + frame-pair tiling --------
        // M rows come straight from global (__ldg, L1-resident, shared by all
        // CTAs). fr rows are broadcast float4 LDS. Writes go into the
        // deinterleaved layout: even-d -> E half, odd-d -> O half (disjoint
        // bank halves: conflict-free mixed-parity stores).
        {
            int npair = (nf + 1) >> 1;
            for (int idx = tid; idx < npair * FCL; idx += NTHREADS) {
                int p = idx / FCL, d = idx - p * FCL;
                int fi0 = 2 * p;
                const float4* M4 = (const float4*)&g_M[d * MSTRIDE];
                const float4* F0 = (const float4*)&sFr[fi0][0];
                const float4* F1 = (const float4*)&sFr[fi0 + 1][0];
                float a0e = 0.f, a0o = 0.f, a1e = 0.f, a1o = 0.f;
                #pragma unroll
                for (int k4 = 0; k4 < 16; ++k4) {
                    float4 m = __ldg(&M4[k4]);
                    float4 x = F0[k4];
                    float4 y = F1[k4];
                    a0e = fmaf(m.x, x.x, a0e); a0o = fmaf(m.y, x.y, a0o);
                    a0e = fmaf(m.z, x.z, a0e); a0o = fmaf(m.w, x.w, a0o);
                    a1e = fmaf(m.x, y.x, a1e); a1o = fmaf(m.y, y.y, a1o);
                    a1e = fmaf(m.z, y.z, a1e); a1o = fmaf(m.w, y.w, a1o);
                }
                float m64 = __ldg(&g_M[d * MSTRIDE + 64]);
                float a0 = a0e + a0o + m64 * sFr[fi0][64];
                float a1 = a1e + a1o + m64 * sFr[fi0 + 1][64];
                float whi = sWin[64 + d], wlo = sWin[64 - d];
                // Wfull[128+d] and Wfull[128-d] both have parity(d).
                int hiAddr, loAddr;
                if (d & 1) { hiAddr = OOFF + ((127 + d) >> 1); loAddr = OOFF + ((127 - d) >> 1); }
                else       { hiAddr = 64 + (d >> 1);           loAddr = 64 - (d >> 1); }
                sWir[fi0][hiAddr]     = a0 * whi;
                sWir[fi0][loAddr]     = a0 * wlo;
                sWir[fi0 + 1][hiAddr] = a1 * whi;
                sWir[fi0 + 1][loAddr] = a1 * wlo;
            }
        }
        __syncthreads();

        // -------- phase 2: direct conv + overlap-add, 6 outputs/lane --------
        // lane owns j0=6*lane..+5; rolling 6-reg window, one fresh tap per step.
        // Fresh tap index 64+j0-(i+1) has uniform parity across the warp:
        //   i even -> O[31+3l-i/2],  i odd -> E[31+3l-(i-1)/2]   (stride 3, no conflicts)
        for (int pass = 0; pass * 8 < nf; ++pass) {
            int fi = pass * 8 + wid;
            if (fi < nf) {
                int g  = g0 + 3 * fi;
                int t3 = 3 * lane;
                const float*  E  = &sWir[fi][0];
                const float*  O  = &sWir[fi][OOFF];
                const float4* N4 = (const float4*)&sN[fi][0];
                // init window: w_r = Wfull[64+6*lane+r]
                float w0 = E[32 + t3], w1 = O[32 + t3], w2 = E[33 + t3];
                float w3 = O[33 + t3], w4 = E[34 + t3], w5 = O[34 + t3];
                float a0 = 0.f, a1 = 0.f, a2 = 0.f, a3 = 0.f, a4 = 0.f, a5 = 0.f;
                #pragma unroll
                for (int i4 = 0; i4 < 16; ++i4) {
                    float4 nv = N4[i4];
                    int k2 = 2 * i4;             // i = 4*i4 -> k = i/2 = 2*i4
                    float f0t = O[31 + t3 - k2];        // fresh for i=4*i4   (even)
                    float f1t = E[31 + t3 - k2];        // fresh for i=4*i4+1 (odd)
                    float f2t = O[30 + t3 - k2];        // fresh for i=4*i4+2
                    float f3t = E[30 + t3 - k2];        // fresh for i=4*i4+3
                    a0 = fmaf(nv.x, w0, a0); a1 = fmaf(nv.x, w1, a1); a2 = fmaf(nv.x, w2, a2);
                    a3 = fmaf(nv.x, w3, a3); a4 = fmaf(nv.x, w4, a4); a5 = fmaf(nv.x, w5, a5);
                    w5 = w4; w4 = w3; w3 = w2; w2 = w1; w1 = w0; w0 = f0t;
                    a0 = fmaf(nv.y, w0, a0); a1 = fmaf(nv.y, w1, a1); a2 = fmaf(nv.y, w2, a2);
                    a3 = fmaf(nv.y, w3, a3); a4 = fmaf(nv.y, w4, a4); a5 = fmaf(nv.y, w5, a5);
                    w5 = w4; w4 = w3; w3 = w2; w2 = w1; w1 = w0; w0 = f1t;
                    a0 = fmaf(nv.z, w0, a0); a1 = fmaf(nv.z, w1, a1); a2 = fmaf(nv.z, w2, a2);
                    a3 = fmaf(nv.z, w3, a3); a4 = fmaf(nv.z, w4, a4); a5 = fmaf(nv.z, w5, a5);
                    w5 = w4; w4 = w3; w3 = w2; w2 = w1; w1 = w0; w0 = f2t;
                    a0 = fmaf(nv.w, w0, a0); a1 = fmaf(nv.w, w1, a1); a2 = fmaf(nv.w, w2, a2);
                    a3 = fmaf(nv.w, w3, a3); a4 = fmaf(nv.w, w4, a4); a5 = fmaf(nv.w, w5, a5);
                    w5 = w4; w4 = w3; w3 = w2; w2 = w1; w1 = w0; w0 = f3t;
                }
                // overlap-add: output element base+r, base = (g-f0)*64 + 6*lane (even).
                // r even -> sAccE[b2 + r/2], r odd -> sAccO[b2 + r/2]  (stride 3)
                int b2 = (g - f0) * 32 + t3;     // halved index, in [-64, 1085]
                if (b2 >= 0 && b2 + 2 < HACC) {
                    sAccE[b2]     += a0; sAccO[b2]     += a1;
                    sAccE[b2 + 1] += a2; sAccO[b2 + 1] += a3;
                    sAccE[b2 + 2] += a4; sAccO[b2 + 2] += a5;
                } else {
                    if (b2     >= 0 && b2     < HACC) { sAccE[b2]     += a0; sAccO[b2]     += a1; }
                    if (b2 + 1 >= 0 && b2 + 1 < HACC) { sAccE[b2 + 1] += a2; sAccO[b2 + 1] += a3; }
                    if (b2 + 2 >= 0 && b2 + 2 < HACC) { sAccE[b2 + 2] += a4; sAccO[b2 + 2] += a5; }
                }
            }
        }
        __syncthreads();
    }

    // epilogue: re-interleave accumulator halves and store as float2
    float2* op2 = (float2*)(out + (size_t)b * SAMPLES + (size_t)f0 * FL);
    for (int i = tid; i < HACC; i += NTHREADS) {
        float2 v; v.x = sAccE[i]; v.y = sAccO[i];
        op2[i] = v;
    }
}

extern "C" void kernel_launch(void* const* d_in, const int* in_sizes, int n_in,
                              void* d_out, int out_size) {
    const float* coef  = (const float*)d_in[0];
    const float* noise = (const float*)d_in[1];
    if (in_sizes[0] != NBATCH * NFRAMES * FCL) {
        const float* t = coef; coef = noise; noise = t;
    }
    init_tables<<<1, 256>>>();
    dim3 grid(CHUNKS, NBATCH);
    filtered_noise_kernel<<<grid, NTHREADS>>>(coef, noise, (float*)d_out);
}